// round 14
// baseline (speedup 1.0000x reference)
#include <cuda_runtime.h>

// FastIMDCT4: B=32, T=1024, n_fft=2048, hop=1024.
// signal: (32, 1024, 1024) f32, window: (2048,) f32
// out: (32, 1, 1, 1047552) f32, y[b, 1024*t + r] = frames[t][1024+r] + frames[t+1][r]
//
// Block: 512 threads = 8 FFT groups x 64 threads -> 7 output chunks.
// 512-pt FFT = 3 in-place DIF radix-8 stages, packed f32x2 butterflies,
// XOR-swizzled conflict-free smem exchanges. 3 named barriers (the stage-2
// WAR hazard is same-warp only: writer i+64rp is read solely by i^(8(rp&1)),
// which the lane remap keeps inside the writer's warp; warp-ordered smem
// traffic + full DFT dataflow make the 4th barrier redundant). 32 KB static
// smem, 4 blocks/SM.

static constexpr int OUTW = 1023 * 1024;

using u64 = unsigned long long;

__device__ __forceinline__ u64 pack2(float x, float y) {
    u64 r; asm("mov.b64 %0,{%1,%2};" : "=l"(r) : "f"(x), "f"(y)); return r;
}
__device__ __forceinline__ float2 unpack2(u64 a) {
    float2 f; asm("mov.b64 {%0,%1},%2;" : "=f"(f.x), "=f"(f.y) : "l"(a)); return f;
}
__device__ __forceinline__ u64 padd(u64 a, u64 b) {
    u64 r; asm("add.rn.f32x2 %0,%1,%2;" : "=l"(r) : "l"(a), "l"(b)); return r;
}
__device__ __forceinline__ u64 pmul(u64 a, u64 b) {
    u64 r; asm("mul.rn.f32x2 %0,%1,%2;" : "=l"(r) : "l"(a), "l"(b)); return r;
}
__device__ __forceinline__ u64 pfma(u64 a, u64 b, u64 c) {
    u64 r; asm("fma.rn.f32x2 %0,%1,%2,%3;" : "=l"(r) : "l"(a), "l"(b), "l"(c)); return r;
}

__device__ __forceinline__ float2 cmulf(float2 a, float2 b) {
    return make_float2(a.x * b.x - a.y * b.y, a.x * b.y + a.y * b.x);
}
__device__ __forceinline__ u64 cmul_pk(u64 a, float2 b) {
    float2 s = unpack2(a);
    return pack2(s.x * b.x - s.y * b.y, s.x * b.y + s.y * b.x);
}

// In-place DIF radix-8, packed (lo=Re, hi=Im). X[n] = v[BR[n]], BR={0,4,2,6,1,5,3,7}.
__device__ __forceinline__ void dft8_pk(u64* v) {
    const u64 M1 = 0xBF800000BF800000ULL;   // (-1,-1)
    const u64 CC = 0x3F3504F33F3504F3ULL;   // (C,C), C = 1/sqrt(2)
    u64 t; float2 s;
    t = pfma(v[4], M1, v[0]); v[0] = padd(v[0], v[4]); v[4] = t;
    t = pfma(v[5], M1, v[1]); v[1] = padd(v[1], v[5]);
    s = unpack2(t); v[5] = pmul(pack2(s.x + s.y, s.y - s.x), CC);       // * W8^1
    t = pfma(v[6], M1, v[2]); v[2] = padd(v[2], v[6]);
    s = unpack2(t); v[6] = pack2(s.y, -s.x);                            // * -i
    t = pfma(v[7], M1, v[3]); v[3] = padd(v[3], v[7]);
    s = unpack2(t); v[7] = pmul(pack2(s.y - s.x, -s.x - s.y), CC);      // * W8^3
    t = pfma(v[2], M1, v[0]); v[0] = padd(v[0], v[2]); v[2] = t;
    t = pfma(v[3], M1, v[1]); v[1] = padd(v[1], v[3]);
    s = unpack2(t); v[3] = pack2(s.y, -s.x);
    t = pfma(v[6], M1, v[4]); v[4] = padd(v[4], v[6]); v[6] = t;
    t = pfma(v[7], M1, v[5]); v[5] = padd(v[5], v[7]);
    s = unpack2(t); v[7] = pack2(s.y, -s.x);
    t = pfma(v[1], M1, v[0]); v[0] = padd(v[0], v[1]); v[1] = t;
    t = pfma(v[3], M1, v[2]); v[2] = padd(v[2], v[3]); v[3] = t;
    t = pfma(v[5], M1, v[4]); v[4] = padd(v[4], v[5]); v[5] = t;
    t = pfma(v[7], M1, v[6]); v[6] = padd(v[6], v[7]); v[7] = t;
}

__global__ __launch_bounds__(512, 4)
void imdct_kernel(const float* __restrict__ sig,
                  const float* __restrict__ win,
                  float* __restrict__ out)
{
    __shared__ float2 fbuf[8][512];   // 32 KB

    const int tid = threadIdx.x;
    const int t0  = blockIdx.x * 7;
    const int b   = blockIdx.y;
    const int fid = tid >> 6;

    // lane remap: each 16-lane LDS phase is 16 consecutive, 16-aligned i values;
    // mirror partner 63-i sits at lane^16 within the same warp; i^8 also stays
    // in-warp (bit-3 flip within {0-15},{48-63} / {16-47}).
    const int u = tid & 63;
    const int q = u >> 4;
    const int i = (q == 0) ? u : (q == 1) ? (79 - u) : (q == 2) ? (u - 16) : (95 - u);

    const int BR[8] = {0, 4, 2, 6, 1, 5, 3, 7};
    const float2 SP[8] = {
        { 1.0f, 0.0f },
        { 0.980785280403230449f, -0.195090322016128268f },
        { 0.923879532511286756f, -0.382683432365089772f },
        { 0.831469612302545237f, -0.555570233019602225f },
        { 0.707106781186547524f, -0.707106781186547524f },
        { 0.555570233019602225f, -0.831469612302545237f },
        { 0.382683432365089772f, -0.923879532511286756f },
        { 0.195090322016128268f, -0.980785280403230449f }
    };

    u64 v[8];

    // ---- load + pre-twiddle in mirror pairs (r, 7-r):
    // re(kk) = F[kk].x; im(kk) = F[511-kk].y via partner lane (^16)
    {
        const int gf = t0 + fid;
        const bool valid = gf < 1024;
        const float2* F = (const float2*)(sig + ((size_t)(b * 1024 + (valid ? gf : 0))) * 1024);
        float bs, bc;
        __sincosf(-6.283185307179586f * ((float)i + 0.125f) * (1.0f / 2048.0f), &bs, &bc);
        const float2 base = make_float2(bc, bs);
        #pragma unroll
        for (int rp = 0; rp < 4; rp++) {
            float2 ga = valid ? F[i + 64 * rp]       : make_float2(0.f, 0.f);
            float2 gb = valid ? F[i + 64 * (7 - rp)] : make_float2(0.f, 0.f);
            float ima = __shfl_xor_sync(0xffffffffu, gb.y, 16);
            float imb = __shfl_xor_sync(0xffffffffu, ga.y, 16);
            float2 ta = cmulf(base, SP[rp]);
            float2 tb = cmulf(base, SP[7 - rp]);
            v[rp]     = pack2(ga.x * ta.x - ima * ta.y, ga.x * ta.y + ima * ta.x);
            v[7 - rp] = pack2(gb.x * tb.x - imb * tb.y, gb.x * tb.y + imb * tb.x);
        }
    }

    u64* fbq = (u64*)fbuf[fid];

    // ---- stage 0: logical fb[8i + rp] = X[rp] * W512^{i*rp}, stored at S1
    dft8_pk(v);
    {
        const int xw = ((i >> 3) & 1) | (((i >> 1) & 1) << 1) | (((i >> 2) & 1) << 2);
        float ws, wc;
        __sincosf(-6.283185307179586f * (float)i * (1.0f / 512.0f), &ws, &wc);
        float2 t1 = make_float2(wc, ws);
        float2 t2 = cmulf(t1, t1);
        float2 t3 = cmulf(t1, t2);
        float2 t4 = cmulf(t2, t2);
        const int bse = 8 * i;
        fbq[bse + (0 ^ xw)] = v[BR[0]];
        fbq[bse + (1 ^ xw)] = cmul_pk(v[BR[1]], t1);
        fbq[bse + (2 ^ xw)] = cmul_pk(v[BR[2]], t2);
        fbq[bse + (3 ^ xw)] = cmul_pk(v[BR[3]], t3);
        fbq[bse + (4 ^ xw)] = cmul_pk(v[BR[4]], t4);
        fbq[bse + (5 ^ xw)] = cmul_pk(v[BR[5]], cmulf(t1, t4));
        fbq[bse + (6 ^ xw)] = cmul_pk(v[BR[6]], cmulf(t2, t4));
        fbq[bse + (7 ^ xw)] = cmul_pk(v[BR[7]], cmulf(t3, t4));
    }
    asm volatile("bar.sync %0, 64;" :: "r"(fid + 1) : "memory");

    // ---- stage 1: load logical i+64r via S1; write logical o+8rp via S2
    {
        const int xr0 = (((i >> 4) & 1) << 1) | (((i >> 5) & 1) << 2);
        #pragma unroll
        for (int r = 0; r < 8; r++)
            v[r] = fbq[(i ^ xr0 ^ (r & 1)) + 64 * r];
    }
    asm volatile("bar.sync %0, 64;" :: "r"(fid + 1) : "memory");
    dft8_pk(v);
    {
        const int j = i >> 3, k = i & 7;
        const int jb = (j & 1);
        float ws, wc;
        __sincosf(-6.283185307179586f * (float)j * (1.0f / 64.0f), &ws, &wc);
        float2 t1 = make_float2(wc, ws);
        float2 t2 = cmulf(t1, t1);
        float2 t3 = cmulf(t1, t2);
        float2 t4 = cmulf(t2, t2);
        const int o = k + 64 * j;
        fbq[o + 8 * (0 ^ jb)] = v[BR[0]];
        fbq[o + 8 * (1 ^ jb)] = cmul_pk(v[BR[1]], t1);
        fbq[o + 8 * (2 ^ jb)] = cmul_pk(v[BR[2]], t2);
        fbq[o + 8 * (3 ^ jb)] = cmul_pk(v[BR[3]], t3);
        fbq[o + 8 * (4 ^ jb)] = cmul_pk(v[BR[4]], t4);
        fbq[o + 8 * (5 ^ jb)] = cmul_pk(v[BR[5]], cmulf(t1, t4));
        fbq[o + 8 * (6 ^ jb)] = cmul_pk(v[BR[6]], cmulf(t2, t4));
        fbq[o + 8 * (7 ^ jb)] = cmul_pk(v[BR[7]], cmulf(t3, t4));
    }
    asm volatile("bar.sync %0, 64;" :: "r"(fid + 1) : "memory");

    // ---- stage 2: load logical i+64r via S2; post-twiddle; store inter[] m-order.
    // NO barrier between load and store: writer slot i+64rp is only read by
    // thread i^(8(rp&1)) (same warp); every STS data-depends on all 8 LDS via
    // the full DFT-8, and same-warp smem ops are serviced in program order.
    {
        #pragma unroll
        for (int r = 0; r < 8; r++)
            v[r] = fbq[(i ^ (8 * (r & 1))) + 64 * r];
    }
    dft8_pk(v);
    {
        float bs2, bc2;
        __sincosf(-6.283185307179586f * ((float)i + 0.125f) * (1.0f / 2048.0f), &bs2, &bc2);
        const float2 base2 = make_float2(bc2, bs2);
        #pragma unroll
        for (int rp = 0; rp < 8; rp++) {
            float2 tw = cmulf(base2, SP[rp]);
            fbq[i + 64 * rp] = cmul_pk(v[BR[rp]], tw);
        }
    }

    // ---- output constants (late, short live ranges) ----
    const bool odd = (tid & 1) != 0;
    const float inv = 1.0f / 512.0f;
    float w0 = win[tid]        * inv;
    float w1 = win[tid + 512]  * inv;
    float w2 = win[tid + 1024] * inv;
    float w3 = win[tid + 1536] * inv;
    const float wA0 = odd ? -w2 : w2;
    const float wA1 = odd ?  w3 : -w3;
    const float wB0 = odd ? -w0 : w0;
    const float wB1 = odd ? -w1 : w1;
    const int mA0 = odd ? (511 - tid)  : (513 + tid);
    const int mA1 = odd ? (1024 - tid) : tid;
    const int mB0 = odd ? (512 - tid)  : (512 + tid);
    const int mB1 = odd ? (1023 - tid) : (tid + 1);

    __syncthreads();

    // ---- output: chunk c -> out[t0+c][r] = inter_c[mA]*wA + inter_{c+1}[mB]*wB
    {
        const float* bse = (const float*)fbuf;   // frame f at bse + f*1024 floats
        float* op = out + (size_t)b * OUTW + (size_t)t0 * 1024 + tid;
        if (t0 <= 1016) {
            // fast path: all 7 chunks valid, no per-iteration guard
            #pragma unroll
            for (int c = 0; c < 7; c++) {
                const float* f0 = bse + c * 1024;
                const float* f1 = bse + (c + 1) * 1024;
                op[0]   = f0[mA0] * wA0 + f1[mB0] * wB0;
                op[512] = f0[mA1] * wA1 + f1[mB1] * wB1;
                op += 1024;
            }
        } else {
            const int nc = 1023 - t0;   // grid tail block only
            for (int c = 0; c < nc; c++) {
                const float* f0 = bse + c * 1024;
                const float* f1 = bse + (c + 1) * 1024;
                op[0]   = f0[mA0] * wA0 + f1[mB0] * wB0;
                op[512] = f0[mA1] * wA1 + f1[mB1] * wB1;
                op += 1024;
            }
        }
    }
}

extern "C" void kernel_launch(void* const* d_in, const int* in_sizes, int n_in,
                              void* d_out, int out_size) {
    const float* sig = (const float*)d_in[0];
    const float* win = (const float*)d_in[1];
    float* out = (float*)d_out;
    dim3 grid(147, 32);   // 147*7 = 1029 >= 1023 chunks
    imdct_kernel<<<grid, 512>>>(sig, win, out);
}

// round 15
// speedup vs baseline: 1.0005x; 1.0005x over previous
#include <cuda_runtime.h>

// FastIMDCT4: B=32, T=1024, n_fft=2048, hop=1024.
// signal: (32, 1024, 1024) f32, window: (2048,) f32
// out: (32, 1, 1, 1047552) f32, y[b, 1024*t + r] = frames[t][1024+r] + frames[t+1][r]
//
// Block: 512 threads = 8 FFT groups x 64 threads -> 7 output chunks.
// 512-pt FFT = 3 in-place DIF radix-8 stages, packed f32x2 butterflies,
// XOR-swizzled conflict-free smem exchanges, 3 named barriers (stage-2 WAR is
// same-warp only — proven R13/R14, verified by unchanged rel_err). 32 KB static
// smem, 4 blocks/SM. Output via streaming stores (write-once, evict-first).

static constexpr int OUTW = 1023 * 1024;

using u64 = unsigned long long;

__device__ __forceinline__ u64 pack2(float x, float y) {
    u64 r; asm("mov.b64 %0,{%1,%2};" : "=l"(r) : "f"(x), "f"(y)); return r;
}
__device__ __forceinline__ float2 unpack2(u64 a) {
    float2 f; asm("mov.b64 {%0,%1},%2;" : "=f"(f.x), "=f"(f.y) : "l"(a)); return f;
}
__device__ __forceinline__ u64 padd(u64 a, u64 b) {
    u64 r; asm("add.rn.f32x2 %0,%1,%2;" : "=l"(r) : "l"(a), "l"(b)); return r;
}
__device__ __forceinline__ u64 pmul(u64 a, u64 b) {
    u64 r; asm("mul.rn.f32x2 %0,%1,%2;" : "=l"(r) : "l"(a), "l"(b)); return r;
}
__device__ __forceinline__ u64 pfma(u64 a, u64 b, u64 c) {
    u64 r; asm("fma.rn.f32x2 %0,%1,%2,%3;" : "=l"(r) : "l"(a), "l"(b), "l"(c)); return r;
}

__device__ __forceinline__ float2 cmulf(float2 a, float2 b) {
    return make_float2(a.x * b.x - a.y * b.y, a.x * b.y + a.y * b.x);
}
__device__ __forceinline__ u64 cmul_pk(u64 a, float2 b) {
    float2 s = unpack2(a);
    return pack2(s.x * b.x - s.y * b.y, s.x * b.y + s.y * b.x);
}

// In-place DIF radix-8, packed (lo=Re, hi=Im). X[n] = v[BR[n]], BR={0,4,2,6,1,5,3,7}.
__device__ __forceinline__ void dft8_pk(u64* v) {
    const u64 M1 = 0xBF800000BF800000ULL;   // (-1,-1)
    const u64 CC = 0x3F3504F33F3504F3ULL;   // (C,C), C = 1/sqrt(2)
    u64 t; float2 s;
    t = pfma(v[4], M1, v[0]); v[0] = padd(v[0], v[4]); v[4] = t;
    t = pfma(v[5], M1, v[1]); v[1] = padd(v[1], v[5]);
    s = unpack2(t); v[5] = pmul(pack2(s.x + s.y, s.y - s.x), CC);       // * W8^1
    t = pfma(v[6], M1, v[2]); v[2] = padd(v[2], v[6]);
    s = unpack2(t); v[6] = pack2(s.y, -s.x);                            // * -i
    t = pfma(v[7], M1, v[3]); v[3] = padd(v[3], v[7]);
    s = unpack2(t); v[7] = pmul(pack2(s.y - s.x, -s.x - s.y), CC);      // * W8^3
    t = pfma(v[2], M1, v[0]); v[0] = padd(v[0], v[2]); v[2] = t;
    t = pfma(v[3], M1, v[1]); v[1] = padd(v[1], v[3]);
    s = unpack2(t); v[3] = pack2(s.y, -s.x);
    t = pfma(v[6], M1, v[4]); v[4] = padd(v[4], v[6]); v[6] = t;
    t = pfma(v[7], M1, v[5]); v[5] = padd(v[5], v[7]);
    s = unpack2(t); v[7] = pack2(s.y, -s.x);
    t = pfma(v[1], M1, v[0]); v[0] = padd(v[0], v[1]); v[1] = t;
    t = pfma(v[3], M1, v[2]); v[2] = padd(v[2], v[3]); v[3] = t;
    t = pfma(v[5], M1, v[4]); v[4] = padd(v[4], v[5]); v[5] = t;
    t = pfma(v[7], M1, v[6]); v[6] = padd(v[6], v[7]); v[7] = t;
}

__global__ __launch_bounds__(512, 4)
void imdct_kernel(const float* __restrict__ sig,
                  const float* __restrict__ win,
                  float* __restrict__ out)
{
    __shared__ float2 fbuf[8][512];   // 32 KB

    const int tid = threadIdx.x;
    const int t0  = blockIdx.x * 7;
    const int b   = blockIdx.y;
    const int fid = tid >> 6;

    // lane remap: each 16-lane LDS phase is 16 consecutive, 16-aligned i values;
    // mirror partner 63-i sits at lane^16 within the same warp; i^8 also stays
    // in-warp (bit-3 flip within {0-15},{48-63} / {16-47}).
    const int u = tid & 63;
    const int q = u >> 4;
    const int i = (q == 0) ? u : (q == 1) ? (79 - u) : (q == 2) ? (u - 16) : (95 - u);

    const int BR[8] = {0, 4, 2, 6, 1, 5, 3, 7};
    const float2 SP[8] = {
        { 1.0f, 0.0f },
        { 0.980785280403230449f, -0.195090322016128268f },
        { 0.923879532511286756f, -0.382683432365089772f },
        { 0.831469612302545237f, -0.555570233019602225f },
        { 0.707106781186547524f, -0.707106781186547524f },
        { 0.555570233019602225f, -0.831469612302545237f },
        { 0.382683432365089772f, -0.923879532511286756f },
        { 0.195090322016128268f, -0.980785280403230449f }
    };

    u64 v[8];

    // ---- load + pre-twiddle in mirror pairs (r, 7-r):
    // re(kk) = F[kk].x; im(kk) = F[511-kk].y via partner lane (^16)
    {
        const int gf = t0 + fid;
        const bool valid = gf < 1024;
        const float2* F = (const float2*)(sig + ((size_t)(b * 1024 + (valid ? gf : 0))) * 1024);
        float bs, bc;
        __sincosf(-6.283185307179586f * ((float)i + 0.125f) * (1.0f / 2048.0f), &bs, &bc);
        const float2 base = make_float2(bc, bs);
        #pragma unroll
        for (int rp = 0; rp < 4; rp++) {
            float2 ga = valid ? F[i + 64 * rp]       : make_float2(0.f, 0.f);
            float2 gb = valid ? F[i + 64 * (7 - rp)] : make_float2(0.f, 0.f);
            float ima = __shfl_xor_sync(0xffffffffu, gb.y, 16);
            float imb = __shfl_xor_sync(0xffffffffu, ga.y, 16);
            float2 ta = cmulf(base, SP[rp]);
            float2 tb = cmulf(base, SP[7 - rp]);
            v[rp]     = pack2(ga.x * ta.x - ima * ta.y, ga.x * ta.y + ima * ta.x);
            v[7 - rp] = pack2(gb.x * tb.x - imb * tb.y, gb.x * tb.y + imb * tb.x);
        }
    }

    u64* fbq = (u64*)fbuf[fid];

    // ---- stage 0: logical fb[8i + rp] = X[rp] * W512^{i*rp}, stored at S1
    dft8_pk(v);
    {
        const int xw = ((i >> 3) & 1) | (((i >> 1) & 1) << 1) | (((i >> 2) & 1) << 2);
        float ws, wc;
        __sincosf(-6.283185307179586f * (float)i * (1.0f / 512.0f), &ws, &wc);
        float2 t1 = make_float2(wc, ws);
        float2 t2 = cmulf(t1, t1);
        float2 t3 = cmulf(t1, t2);
        float2 t4 = cmulf(t2, t2);
        const int bse = 8 * i;
        fbq[bse + (0 ^ xw)] = v[BR[0]];
        fbq[bse + (1 ^ xw)] = cmul_pk(v[BR[1]], t1);
        fbq[bse + (2 ^ xw)] = cmul_pk(v[BR[2]], t2);
        fbq[bse + (3 ^ xw)] = cmul_pk(v[BR[3]], t3);
        fbq[bse + (4 ^ xw)] = cmul_pk(v[BR[4]], t4);
        fbq[bse + (5 ^ xw)] = cmul_pk(v[BR[5]], cmulf(t1, t4));
        fbq[bse + (6 ^ xw)] = cmul_pk(v[BR[6]], cmulf(t2, t4));
        fbq[bse + (7 ^ xw)] = cmul_pk(v[BR[7]], cmulf(t3, t4));
    }
    asm volatile("bar.sync %0, 64;" :: "r"(fid + 1) : "memory");

    // ---- stage 1: load logical i+64r via S1; write logical o+8rp via S2
    {
        const int xr0 = (((i >> 4) & 1) << 1) | (((i >> 5) & 1) << 2);
        #pragma unroll
        for (int r = 0; r < 8; r++)
            v[r] = fbq[(i ^ xr0 ^ (r & 1)) + 64 * r];
    }
    asm volatile("bar.sync %0, 64;" :: "r"(fid + 1) : "memory");
    dft8_pk(v);
    {
        const int j = i >> 3, k = i & 7;
        const int jb = (j & 1);
        float ws, wc;
        __sincosf(-6.283185307179586f * (float)j * (1.0f / 64.0f), &ws, &wc);
        float2 t1 = make_float2(wc, ws);
        float2 t2 = cmulf(t1, t1);
        float2 t3 = cmulf(t1, t2);
        float2 t4 = cmulf(t2, t2);
        const int o = k + 64 * j;
        fbq[o + 8 * (0 ^ jb)] = v[BR[0]];
        fbq[o + 8 * (1 ^ jb)] = cmul_pk(v[BR[1]], t1);
        fbq[o + 8 * (2 ^ jb)] = cmul_pk(v[BR[2]], t2);
        fbq[o + 8 * (3 ^ jb)] = cmul_pk(v[BR[3]], t3);
        fbq[o + 8 * (4 ^ jb)] = cmul_pk(v[BR[4]], t4);
        fbq[o + 8 * (5 ^ jb)] = cmul_pk(v[BR[5]], cmulf(t1, t4));
        fbq[o + 8 * (6 ^ jb)] = cmul_pk(v[BR[6]], cmulf(t2, t4));
        fbq[o + 8 * (7 ^ jb)] = cmul_pk(v[BR[7]], cmulf(t3, t4));
    }
    asm volatile("bar.sync %0, 64;" :: "r"(fid + 1) : "memory");

    // ---- stage 2: load logical i+64r via S2; post-twiddle; store inter[] m-order.
    // NO barrier between load and store: writer slot i+64rp is only read by
    // thread i^(8(rp&1)) (same warp); every STS data-depends on all 8 LDS via
    // the full DFT-8, and same-warp smem ops are serviced in program order.
    {
        #pragma unroll
        for (int r = 0; r < 8; r++)
            v[r] = fbq[(i ^ (8 * (r & 1))) + 64 * r];
    }
    dft8_pk(v);
    {
        float bs2, bc2;
        __sincosf(-6.283185307179586f * ((float)i + 0.125f) * (1.0f / 2048.0f), &bs2, &bc2);
        const float2 base2 = make_float2(bc2, bs2);
        #pragma unroll
        for (int rp = 0; rp < 8; rp++) {
            float2 tw = cmulf(base2, SP[rp]);
            fbq[i + 64 * rp] = cmul_pk(v[BR[rp]], tw);
        }
    }

    // ---- output constants (late, short live ranges) ----
    const bool odd = (tid & 1) != 0;
    const float inv = 1.0f / 512.0f;
    float w0 = win[tid]        * inv;
    float w1 = win[tid + 512]  * inv;
    float w2 = win[tid + 1024] * inv;
    float w3 = win[tid + 1536] * inv;
    const float wA0 = odd ? -w2 : w2;
    const float wA1 = odd ?  w3 : -w3;
    const float wB0 = odd ? -w0 : w0;
    const float wB1 = odd ? -w1 : w1;
    const int mA0 = odd ? (511 - tid)  : (513 + tid);
    const int mA1 = odd ? (1024 - tid) : tid;
    const int mB0 = odd ? (512 - tid)  : (512 + tid);
    const int mB1 = odd ? (1023 - tid) : (tid + 1);

    __syncthreads();

    // ---- output: chunk c -> out[t0+c][r] = inter_c[mA]*wA + inter_{c+1}[mB]*wB
    // Streaming stores: output is write-once, keep it out of L2's way.
    {
        const float* bse = (const float*)fbuf;   // frame f at bse + f*1024 floats
        float* op = out + (size_t)b * OUTW + (size_t)t0 * 1024 + tid;
        if (t0 <= 1016) {
            #pragma unroll
            for (int c = 0; c < 7; c++) {
                const float* f0 = bse + c * 1024;
                const float* f1 = bse + (c + 1) * 1024;
                __stcs(op,       f0[mA0] * wA0 + f1[mB0] * wB0);
                __stcs(op + 512, f0[mA1] * wA1 + f1[mB1] * wB1);
                op += 1024;
            }
        } else {
            const int nc = 1023 - t0;   // grid tail block only
            for (int c = 0; c < nc; c++) {
                const float* f0 = bse + c * 1024;
                const float* f1 = bse + (c + 1) * 1024;
                __stcs(op,       f0[mA0] * wA0 + f1[mB0] * wB0);
                __stcs(op + 512, f0[mA1] * wA1 + f1[mB1] * wB1);
                op += 1024;
            }
        }
    }
}

extern "C" void kernel_launch(void* const* d_in, const int* in_sizes, int n_in,
                              void* d_out, int out_size) {
    const float* sig = (const float*)d_in[0];
    const float* win = (const float*)d_in[1];
    float* out = (float*)d_out;
    dim3 grid(147, 32);   // 147*7 = 1029 >= 1023 chunks
    imdct_kernel<<<grid, 512>>>(sig, win, out);
}

// round 16
// speedup vs baseline: 1.0732x; 1.0727x over previous
#include <cuda_runtime.h>

// FastIMDCT4: B=32, T=1024, n_fft=2048, hop=1024.
// signal: (32, 1024, 1024) f32, window: (2048,) f32
// out: (32, 1, 1, 1047552) f32, y[b, 1024*t + r] = frames[t][1024+r] + frames[t+1][r]
//
// Block: 512 threads = 8 FFT groups x 64 threads -> 7 output chunks.
// 512-pt FFT = 3 in-place DIF radix-8 stages with packed f32x2 butterflies,
// 2 XOR-swizzled conflict-free smem exchanges. launch_bounds(512,4): 4 resident
// blocks/SM (32-reg cap). Best-measured configuration of the session
// (kernel 60.2us on both prior runs of this exact source).

static constexpr int OUTW = 1023 * 1024;

using u64 = unsigned long long;

__device__ __forceinline__ u64 pack2(float x, float y) {
    u64 r; asm("mov.b64 %0,{%1,%2};" : "=l"(r) : "f"(x), "f"(y)); return r;
}
__device__ __forceinline__ float2 unpack2(u64 a) {
    float2 f; asm("mov.b64 {%0,%1},%2;" : "=f"(f.x), "=f"(f.y) : "l"(a)); return f;
}
__device__ __forceinline__ u64 padd(u64 a, u64 b) {
    u64 r; asm("add.rn.f32x2 %0,%1,%2;" : "=l"(r) : "l"(a), "l"(b)); return r;
}
__device__ __forceinline__ u64 pmul(u64 a, u64 b) {
    u64 r; asm("mul.rn.f32x2 %0,%1,%2;" : "=l"(r) : "l"(a), "l"(b)); return r;
}
__device__ __forceinline__ u64 pfma(u64 a, u64 b, u64 c) {
    u64 r; asm("fma.rn.f32x2 %0,%1,%2,%3;" : "=l"(r) : "l"(a), "l"(b), "l"(c)); return r;
}

__device__ __forceinline__ float2 cmulf(float2 a, float2 b) {
    return make_float2(a.x * b.x - a.y * b.y, a.x * b.y + a.y * b.x);
}
__device__ __forceinline__ u64 cmul_pk(u64 a, float2 b) {
    float2 s = unpack2(a);
    return pack2(s.x * b.x - s.y * b.y, s.x * b.y + s.y * b.x);
}

// In-place DIF radix-8, packed (lo=Re, hi=Im). X[n] = v[BR[n]], BR={0,4,2,6,1,5,3,7}.
__device__ __forceinline__ void dft8_pk(u64* v) {
    const u64 M1 = 0xBF800000BF800000ULL;   // (-1,-1)
    const u64 CC = 0x3F3504F33F3504F3ULL;   // (C,C), C = 1/sqrt(2)
    u64 t; float2 s;
    t = pfma(v[4], M1, v[0]); v[0] = padd(v[0], v[4]); v[4] = t;
    t = pfma(v[5], M1, v[1]); v[1] = padd(v[1], v[5]);
    s = unpack2(t); v[5] = pmul(pack2(s.x + s.y, s.y - s.x), CC);       // * W8^1
    t = pfma(v[6], M1, v[2]); v[2] = padd(v[2], v[6]);
    s = unpack2(t); v[6] = pack2(s.y, -s.x);                            // * -i
    t = pfma(v[7], M1, v[3]); v[3] = padd(v[3], v[7]);
    s = unpack2(t); v[7] = pmul(pack2(s.y - s.x, -s.x - s.y), CC);      // * W8^3
    t = pfma(v[2], M1, v[0]); v[0] = padd(v[0], v[2]); v[2] = t;
    t = pfma(v[3], M1, v[1]); v[1] = padd(v[1], v[3]);
    s = unpack2(t); v[3] = pack2(s.y, -s.x);
    t = pfma(v[6], M1, v[4]); v[4] = padd(v[4], v[6]); v[6] = t;
    t = pfma(v[7], M1, v[5]); v[5] = padd(v[5], v[7]);
    s = unpack2(t); v[7] = pack2(s.y, -s.x);
    t = pfma(v[1], M1, v[0]); v[0] = padd(v[0], v[1]); v[1] = t;
    t = pfma(v[3], M1, v[2]); v[2] = padd(v[2], v[3]); v[3] = t;
    t = pfma(v[5], M1, v[4]); v[4] = padd(v[4], v[5]); v[5] = t;
    t = pfma(v[7], M1, v[6]); v[6] = padd(v[6], v[7]); v[7] = t;
}

__global__ __launch_bounds__(512, 4)
void imdct_kernel(const float* __restrict__ sig,
                  const float* __restrict__ win,
                  float* __restrict__ out)
{
    __shared__ float2 fbuf[8][512];   // 32 KB

    const int tid = threadIdx.x;
    const int t0  = blockIdx.x * 7;
    const int b   = blockIdx.y;
    const int fid = tid >> 6;

    // lane remap: each 16-lane LDS phase is 16 consecutive, 16-aligned i values;
    // mirror partner 63-i sits at lane^16 within the same warp.
    const int u = tid & 63;
    const int q = u >> 4;
    const int i = (q == 0) ? u : (q == 1) ? (79 - u) : (q == 2) ? (u - 16) : (95 - u);

    const int BR[8] = {0, 4, 2, 6, 1, 5, 3, 7};
    const float2 SP[8] = {
        { 1.0f, 0.0f },
        { 0.980785280403230449f, -0.195090322016128268f },
        { 0.923879532511286756f, -0.382683432365089772f },
        { 0.831469612302545237f, -0.555570233019602225f },
        { 0.707106781186547524f, -0.707106781186547524f },
        { 0.555570233019602225f, -0.831469612302545237f },
        { 0.382683432365089772f, -0.923879532511286756f },
        { 0.195090322016128268f, -0.980785280403230449f }
    };

    u64 v[8];

    // ---- load + pre-twiddle in mirror pairs (r, 7-r):
    // re(kk) = F[kk].x; im(kk) = F[511-kk].y via partner lane (^16)
    {
        const int gf = t0 + fid;
        const bool valid = gf < 1024;
        const float2* F = (const float2*)(sig + ((size_t)(b * 1024 + (valid ? gf : 0))) * 1024);
        float bs, bc;
        __sincosf(-6.283185307179586f * ((float)i + 0.125f) * (1.0f / 2048.0f), &bs, &bc);
        const float2 base = make_float2(bc, bs);
        #pragma unroll
        for (int rp = 0; rp < 4; rp++) {
            float2 ga = valid ? F[i + 64 * rp]       : make_float2(0.f, 0.f);
            float2 gb = valid ? F[i + 64 * (7 - rp)] : make_float2(0.f, 0.f);
            float ima = __shfl_xor_sync(0xffffffffu, gb.y, 16);
            float imb = __shfl_xor_sync(0xffffffffu, ga.y, 16);
            float2 ta = cmulf(base, SP[rp]);
            float2 tb = cmulf(base, SP[7 - rp]);
            v[rp]     = pack2(ga.x * ta.x - ima * ta.y, ga.x * ta.y + ima * ta.x);
            v[7 - rp] = pack2(gb.x * tb.x - imb * tb.y, gb.x * tb.y + imb * tb.x);
        }
    }

    u64* fbq = (u64*)fbuf[fid];

    // ---- stage 0: logical fb[8i + rp] = X[rp] * W512^{i*rp}, stored at S1
    dft8_pk(v);
    {
        const int xw = ((i >> 3) & 1) | (((i >> 1) & 1) << 1) | (((i >> 2) & 1) << 2);
        float ws, wc;
        __sincosf(-6.283185307179586f * (float)i * (1.0f / 512.0f), &ws, &wc);
        float2 t1 = make_float2(wc, ws);
        float2 t2 = cmulf(t1, t1);
        float2 t3 = cmulf(t1, t2);
        float2 t4 = cmulf(t2, t2);
        const int bse = 8 * i;
        fbq[bse + (0 ^ xw)] = v[BR[0]];
        fbq[bse + (1 ^ xw)] = cmul_pk(v[BR[1]], t1);
        fbq[bse + (2 ^ xw)] = cmul_pk(v[BR[2]], t2);
        fbq[bse + (3 ^ xw)] = cmul_pk(v[BR[3]], t3);
        fbq[bse + (4 ^ xw)] = cmul_pk(v[BR[4]], t4);
        fbq[bse + (5 ^ xw)] = cmul_pk(v[BR[5]], cmulf(t1, t4));
        fbq[bse + (6 ^ xw)] = cmul_pk(v[BR[6]], cmulf(t2, t4));
        fbq[bse + (7 ^ xw)] = cmul_pk(v[BR[7]], cmulf(t3, t4));
    }
    asm volatile("bar.sync %0, 64;" :: "r"(fid + 1) : "memory");

    // ---- stage 1: load logical i+64r via S1; write logical o+8rp via S2
    {
        const int xr0 = (((i >> 4) & 1) << 1) | (((i >> 5) & 1) << 2);
        #pragma unroll
        for (int r = 0; r < 8; r++)
            v[r] = fbq[(i ^ xr0 ^ (r & 1)) + 64 * r];
    }
    asm volatile("bar.sync %0, 64;" :: "r"(fid + 1) : "memory");
    dft8_pk(v);
    {
        const int j = i >> 3, k = i & 7;
        const int jb = (j & 1);
        float ws, wc;
        __sincosf(-6.283185307179586f * (float)j * (1.0f / 64.0f), &ws, &wc);
        float2 t1 = make_float2(wc, ws);
        float2 t2 = cmulf(t1, t1);
        float2 t3 = cmulf(t1, t2);
        float2 t4 = cmulf(t2, t2);
        const int o = k + 64 * j;
        fbq[o + 8 * (0 ^ jb)] = v[BR[0]];
        fbq[o + 8 * (1 ^ jb)] = cmul_pk(v[BR[1]], t1);
        fbq[o + 8 * (2 ^ jb)] = cmul_pk(v[BR[2]], t2);
        fbq[o + 8 * (3 ^ jb)] = cmul_pk(v[BR[3]], t3);
        fbq[o + 8 * (4 ^ jb)] = cmul_pk(v[BR[4]], t4);
        fbq[o + 8 * (5 ^ jb)] = cmul_pk(v[BR[5]], cmulf(t1, t4));
        fbq[o + 8 * (6 ^ jb)] = cmul_pk(v[BR[6]], cmulf(t2, t4));
        fbq[o + 8 * (7 ^ jb)] = cmul_pk(v[BR[7]], cmulf(t3, t4));
    }
    asm volatile("bar.sync %0, 64;" :: "r"(fid + 1) : "memory");

    // ---- stage 2: load logical i+64r via S2; post-twiddle; store inter[] m-order
    {
        #pragma unroll
        for (int r = 0; r < 8; r++)
            v[r] = fbq[(i ^ (8 * (r & 1))) + 64 * r];
    }
    asm volatile("bar.sync %0, 64;" :: "r"(fid + 1) : "memory");
    dft8_pk(v);
    {
        // recompute base twiddle here (kept out of the long live range)
        float bs2, bc2;
        __sincosf(-6.283185307179586f * ((float)i + 0.125f) * (1.0f / 2048.0f), &bs2, &bc2);
        const float2 base2 = make_float2(bc2, bs2);
        #pragma unroll
        for (int rp = 0; rp < 8; rp++) {
            float2 tw = cmulf(base2, SP[rp]);
            fbq[i + 64 * rp] = cmul_pk(v[BR[rp]], tw);
        }
    }

    // ---- output constants (late, short live ranges) ----
    const bool odd = (tid & 1) != 0;
    const float inv = 1.0f / 512.0f;
    float w0 = win[tid]        * inv;
    float w1 = win[tid + 512]  * inv;
    float w2 = win[tid + 1024] * inv;
    float w3 = win[tid + 1536] * inv;
    const float wA0 = odd ? -w2 : w2;
    const float wA1 = odd ?  w3 : -w3;
    const float wB0 = odd ? -w0 : w0;
    const float wB1 = odd ? -w1 : w1;
    const int mA0 = odd ? (511 - tid)  : (513 + tid);
    const int mA1 = odd ? (1024 - tid) : tid;
    const int mB0 = odd ? (512 - tid)  : (512 + tid);
    const int mB1 = odd ? (1023 - tid) : (tid + 1);

    __syncthreads();

    // ---- output: chunk c -> out[t0+c][r] = inter_c[mA]*wA + inter_{c+1}[mB]*wB
    {
        const float* bse = (const float*)fbuf;   // frame f at bse + f*1024 floats
        float* op = out + (size_t)b * OUTW + (size_t)t0 * 1024 + tid;
        #pragma unroll
        for (int c = 0; c < 7; c++) {
            if (t0 + c > 1022) break;
            const float* f0 = bse + c * 1024;
            const float* f1 = bse + (c + 1) * 1024;
            op[0]   = f0[mA0] * wA0 + f1[mB0] * wB0;
            op[512] = f0[mA1] * wA1 + f1[mB1] * wB1;
            op += 1024;
        }
    }
}

extern "C" void kernel_launch(void* const* d_in, const int* in_sizes, int n_in,
                              void* d_out, int out_size) {
    const float* sig = (const float*)d_in[0];
    const float* win = (const float*)d_in[1];
    float* out = (float*)d_out;
    dim3 grid(147, 32);   // 147*7 = 1029 >= 1023 chunks
    imdct_kernel<<<grid, 512>>>(sig, win, out);
}